// round 9
// baseline (speedup 1.0000x reference)
#include <cuda_runtime.h>

// b=8, nw=256, nn=64, d=128, G=4. windows = 2048, TOK = 64*128 = 8192.
#define NTW 2048
#define TOK 8192
typedef unsigned long long ull;

// Scratch (device globals; no cudaMalloc allowed)
__device__ float g_f [NTW * TOK];   // _f (group-normalized in_f)
__device__ float g_h [NTW * TOK];   // leaky(_f@W1 + b1)
__device__ float g_qp[NTW * TOK];   // _f@Wq (pre group-norm)
__device__ float g_pf[NTW * 8];
__device__ float g_pq[NTW * 8];
__device__ float g_mu[2][32];
__device__ float g_rs[2][32];

// Output layout: flattened float32, tuple order
#define CLF_OFF    0
#define CLM_OFF    2097152
#define CLGEO_OFF  3145728
#define CLR_OFF    3244032
#define CLCOMP_OFF 3258368
#define AF_OFF     3274752
#define SCM_OFF    11663360
#define Q_OFF      11794432

__device__ __forceinline__ float wredsum(float v){
#pragma unroll
    for (int o = 16; o; o >>= 1) v += __shfl_xor_sync(0xffffffffu, v, o);
    return v;
}
__device__ __forceinline__ float wredmax(float v){
#pragma unroll
    for (int o = 16; o; o >>= 1) v = fmaxf(v, __shfl_xor_sync(0xffffffffu, v, o));
    return v;
}
__device__ __forceinline__ float wredmin(float v){
#pragma unroll
    for (int o = 16; o; o >>= 1) v = fminf(v, __shfl_xor_sync(0xffffffffu, v, o));
    return v;
}
__device__ __forceinline__ float clampaf(float v){
    return fminf(fmaxf(v, 1e-5f), 0.99999f);
}

// ---- packed fp32x2 helpers ----
__device__ __forceinline__ void ffma2(ull& acc, ull a, ull b){
    asm("fma.rn.f32x2 %0, %1, %2, %0;" : "+l"(acc) : "l"(a), "l"(b));
}
__device__ __forceinline__ ull dup2(float x){
    ull r; asm("mov.b64 %0, {%1, %1};" : "=l"(r) : "f"(x)); return r;
}
__device__ __forceinline__ void unpack2(ull v, float& lo, float& hi){
    asm("mov.b64 {%0, %1}, %2;" : "=f"(lo), "=f"(hi) : "l"(v));
}
__device__ __forceinline__ float red2(ull v){
    float lo, hi; unpack2(v, lo, hi); return lo + hi;
}

// ============================================================================
// K1: per-window partial stats of in_f per channel group
// ============================================================================
__global__ void __launch_bounds__(256) k_stat(const float* __restrict__ in_f){
    __shared__ float sp[256][2];
    int win = blockIdx.x, t = threadIdx.x;
    const float* X = in_f + (size_t)win * TOK;
    int c = t & 127, h = t >> 7;
    float s = 0.f, ss = 0.f;
    for (int r = h; r < 64; r += 2){
        float v = X[r * 128 + c];
        s += v; ss = fmaf(v, v, ss);
    }
    sp[t][0] = s; sp[t][1] = ss;
    __syncthreads();
    if (t < 4){
        float S = 0.f, SS = 0.f;
        for (int hh = 0; hh < 2; hh++)
            for (int j = 0; j < 32; j++){
                int tt = hh * 128 + t * 32 + j;
                S += sp[tt][0]; SS += sp[tt][1];
            }
        g_pf[win * 8 + t * 2]     = S;
        g_pf[win * 8 + t * 2 + 1] = SS;
    }
}

// ============================================================================
// K2/K4: reduce partials over 256 windows -> mu, rsqrt(var+eps) per (b,g)
// ============================================================================
__global__ void __launch_bounds__(256) k_red(int which){
    __shared__ float sh[256][2];
    int bg = blockIdx.x, t = threadIdx.x;
    const float* P = which ? g_pq : g_pf;
    int win = (bg >> 2) * 256 + t, g = bg & 3;
    sh[t][0] = P[win * 8 + g * 2];
    sh[t][1] = P[win * 8 + g * 2 + 1];
    __syncthreads();
    for (int st = 128; st > 0; st >>= 1){
        if (t < st){ sh[t][0] += sh[t + st][0]; sh[t][1] += sh[t + st][1]; }
        __syncthreads();
    }
    if (t == 0){
        const float N = 524288.0f; // 256*64*32
        float m = sh[0][0] / N;
        float v = sh[0][1] / N - m * m;
        g_mu[which][bg] = m;
        g_rs[which][bg] = rsqrtf(v + 1e-3f);
    }
}

// ============================================================================
// K3: per-window: _f, h = leaky(_f@W1+b1), q_pre = _f@Wq, q-stat partials.
// k-pair interleaved smem layouts feed fma.rn.f32x2 with zero packing cost.
// At2[kk][2*r + (k&1)] pitch 132; Ws2[kk][2*c + (k&1)] pitch 256.
// dynamic smem = (64*132 + 64*256)*4 = 99328 B.
// ============================================================================
__global__ void __launch_bounds__(256) k_mlp(const float* __restrict__ in_f,
                      const float* __restrict__ W1, const float* __restrict__ b1,
                      const float* __restrict__ Wq){
    extern __shared__ float smm[];
    float* At2 = smm;             // 64 * 132 = 8448
    float* Ws2 = smm + 8448;      // 64 * 256 = 16384
    __shared__ float sp[256][2];

    int win = blockIdx.x, t = threadIdx.x, b = win >> 8;

    float mu[4], rv[4];
#pragma unroll
    for (int g = 0; g < 4; g++){ mu[g] = g_mu[0][b*4+g]; rv[g] = g_rs[0][b*4+g]; }

    const float* X = in_f + (size_t)win * TOK;
    float* Fo = g_f + (size_t)win * TOK;
    {
        int c = t & 127, g = c >> 5;
        float m = mu[g], r = rv[g];
        int cbase = (c >> 1) * 132 + (c & 1);
        for (int i = t; i < TOK; i += 256){
            float v = (X[i] - m) * r;
            Fo[i] = v;
            At2[cbase + ((i >> 7) << 1)] = v;
        }
    }
    for (int i = t; i < 16384; i += 256){
        int k = i >> 7, c = i & 127;
        Ws2[(k >> 1) * 256 + (c << 1) + (k & 1)] = W1[i];
    }
    __syncthreads();

    int rb = (t >> 5) * 8, cb = (t & 31) * 4;
    ull acc[8][4];
#pragma unroll
    for (int r = 0; r < 8; r++)
#pragma unroll
        for (int c = 0; c < 4; c++) acc[r][c] = 0ull;

    for (int kk = 0; kk < 64; kk++){
        const float* ab = At2 + kk * 132 + rb * 2;
        ulonglong2 a01 = *reinterpret_cast<const ulonglong2*>(ab);
        ulonglong2 a23 = *reinterpret_cast<const ulonglong2*>(ab + 4);
        ulonglong2 a45 = *reinterpret_cast<const ulonglong2*>(ab + 8);
        ulonglong2 a67 = *reinterpret_cast<const ulonglong2*>(ab + 12);
        const float* wb = Ws2 + kk * 256 + cb * 2;
        ulonglong2 w01 = *reinterpret_cast<const ulonglong2*>(wb);
        ulonglong2 w23 = *reinterpret_cast<const ulonglong2*>(wb + 4);
        ull a[8] = {a01.x,a01.y,a23.x,a23.y,a45.x,a45.y,a67.x,a67.y};
        ull w[4] = {w01.x,w01.y,w23.x,w23.y};
#pragma unroll
        for (int r = 0; r < 8; r++){
            ffma2(acc[r][0], a[r], w[0]);
            ffma2(acc[r][1], a[r], w[1]);
            ffma2(acc[r][2], a[r], w[2]);
            ffma2(acc[r][3], a[r], w[3]);
        }
    }
    {
        float4 bv = *reinterpret_cast<const float4*>(b1 + cb);
        float bb[4] = {bv.x, bv.y, bv.z, bv.w};
        float* Ho = g_h + (size_t)win * TOK;
#pragma unroll
        for (int r = 0; r < 8; r++){
            float4 o; float v;
            v = red2(acc[r][0]) + bb[0]; o.x = v >= 0.f ? v : 0.01f * v;
            v = red2(acc[r][1]) + bb[1]; o.y = v >= 0.f ? v : 0.01f * v;
            v = red2(acc[r][2]) + bb[2]; o.z = v >= 0.f ? v : 0.01f * v;
            v = red2(acc[r][3]) + bb[3]; o.w = v >= 0.f ? v : 0.01f * v;
            *reinterpret_cast<float4*>(Ho + (rb + r) * 128 + cb) = o;
        }
    }
    __syncthreads();
    for (int i = t; i < 16384; i += 256){
        int k = i >> 7, c = i & 127;
        Ws2[(k >> 1) * 256 + (c << 1) + (k & 1)] = Wq[i];
    }
    __syncthreads();

#pragma unroll
    for (int r = 0; r < 8; r++)
#pragma unroll
        for (int c = 0; c < 4; c++) acc[r][c] = 0ull;
    for (int kk = 0; kk < 64; kk++){
        const float* ab = At2 + kk * 132 + rb * 2;
        ulonglong2 a01 = *reinterpret_cast<const ulonglong2*>(ab);
        ulonglong2 a23 = *reinterpret_cast<const ulonglong2*>(ab + 4);
        ulonglong2 a45 = *reinterpret_cast<const ulonglong2*>(ab + 8);
        ulonglong2 a67 = *reinterpret_cast<const ulonglong2*>(ab + 12);
        const float* wb = Ws2 + kk * 256 + cb * 2;
        ulonglong2 w01 = *reinterpret_cast<const ulonglong2*>(wb);
        ulonglong2 w23 = *reinterpret_cast<const ulonglong2*>(wb + 4);
        ull a[8] = {a01.x,a01.y,a23.x,a23.y,a45.x,a45.y,a67.x,a67.y};
        ull w[4] = {w01.x,w01.y,w23.x,w23.y};
#pragma unroll
        for (int r = 0; r < 8; r++){
            ffma2(acc[r][0], a[r], w[0]);
            ffma2(acc[r][1], a[r], w[1]);
            ffma2(acc[r][2], a[r], w[2]);
            ffma2(acc[r][3], a[r], w[3]);
        }
    }
    {
        float* Qo = g_qp + (size_t)win * TOK;
        float s = 0.f, ss = 0.f;
#pragma unroll
        for (int r = 0; r < 8; r++){
            float4 o;
            o.x = red2(acc[r][0]); o.y = red2(acc[r][1]);
            o.z = red2(acc[r][2]); o.w = red2(acc[r][3]);
            *reinterpret_cast<float4*>(Qo + (rb + r) * 128 + cb) = o;
            s  += o.x + o.y + o.z + o.w;
            ss += o.x*o.x + o.y*o.y + o.z*o.z + o.w*o.w;
        }
        sp[t][0] = s; sp[t][1] = ss;
    }
    __syncthreads();
    if (t < 4){
        float S = 0.f, SS = 0.f;
        for (int w2 = 0; w2 < 8; w2++)
            for (int j = 0; j < 8; j++){
                int tt = w2 * 32 + t * 8 + j;
                S += sp[tt][0]; SS += sp[tt][1];
            }
        g_pq[win * 8 + t * 2]     = S;
        g_pq[win * 8 + t * 2 + 1] = SS;
    }
}

// ============================================================================
// K5: per-window mega kernel. dynamic smem = 57632 B.
// ============================================================================
__global__ void __launch_bounds__(256) k_main(const float* __restrict__ in_f,
        const float* __restrict__ in_geo,
        const float* __restrict__ W2,  const float* __restrict__ b2,
        const float* __restrict__ Wfc, const float* __restrict__ bfc,
        const float* __restrict__ Wv,  float* __restrict__ out){
    extern __shared__ float sm[];
    float* QT2  = sm;            // 64*132 = 8448; later reused as scratch
    float* AFs  = sm + 8448;     // [64][68]
    float* DENS = sm + 12800;
    float* AREA = sm + 12864;
    float* INER = sm + 12928;
    float* CX   = sm + 12992;
    float* CY   = sm + 13056;
    float* C2   = sm + 13120;
    float* N2   = sm + 13184;
    float* COMP = sm + 13248;
    float* SCv  = sm + 13312;
    float* CLM  = sm + 13376;    // [8][64]
    float* CLMM = sm + 13888;    // [8][64]
    float* RS   = sm + 14400;    // [8]

    int win = blockIdx.x, t = threadIdx.x;
    int w = t >> 5, lane = t & 31;
    int b = win >> 8;

    if (t < 64){
        const float* gp = in_geo + (size_t)win * 384 + t * 6;
        float dn = gp[0], ar = gp[2], ii = gp[3], x = gp[4], y = gp[5];
        DENS[t]=dn; AREA[t]=ar; INER[t]=ii; CX[t]=x; CY[t]=y; C2[t]=x*x+y*y;
        SCv[t]=1.f;
    }
    // pass1: normalize q_pre -> QT2 (k-pair interleaved) + q out
    {
        float mu[4], rv[4];
#pragma unroll
        for (int g = 0; g < 4; g++){ mu[g]=g_mu[1][b*4+g]; rv[g]=g_rs[1][b*4+g]; }
        const float* Qp = g_qp + (size_t)win * TOK;
        float* Qo = out + Q_OFF + (size_t)win * TOK;
        int c = t & 127, g = c >> 5;
        float m = mu[g], r = rv[g];
        int cbase = (c >> 1) * 132 + (c & 1);
        for (int i = t; i < TOK; i += 256){
            float v = (Qp[i] - m) * r;
            Qo[i] = v;
            QT2[cbase + ((i >> 7) << 1)] = v;
        }
    }
    __syncthreads();
    // pass2: n2 per row
    for (int q = w * 8; q < w * 8 + 8; q++){
        float s = 0.f;
        for (int c = lane; c < 128; c += 32){
            float v = QT2[(c >> 1) * 132 + (q << 1) + (c & 1)];
            s = fmaf(v, v, s);
        }
        s = wredsum(s);
        if (lane == 0) N2[q] = s;
    }
    __syncthreads();
    // pass3: Gram -> logits into AFs (f32x2)
    {
        int ty = t >> 4, tx = t & 15;
        int R = 4 * ty, C = 4 * tx;
        ull acc[4][4];
#pragma unroll
        for (int r = 0; r < 4; r++)
#pragma unroll
            for (int c = 0; c < 4; c++) acc[r][c] = 0ull;
        for (int kk = 0; kk < 64; kk++){
            const float* base = QT2 + kk * 132;
            ulonglong2 aa0 = *reinterpret_cast<const ulonglong2*>(base + R * 2);
            ulonglong2 aa1 = *reinterpret_cast<const ulonglong2*>(base + R * 2 + 4);
            ulonglong2 bb0 = *reinterpret_cast<const ulonglong2*>(base + C * 2);
            ulonglong2 bb1 = *reinterpret_cast<const ulonglong2*>(base + C * 2 + 4);
            ull a[4]  = {aa0.x, aa0.y, aa1.x, aa1.y};
            ull bv[4] = {bb0.x, bb0.y, bb1.x, bb1.y};
#pragma unroll
            for (int r = 0; r < 4; r++){
                ffma2(acc[r][0], a[r], bv[0]);
                ffma2(acc[r][1], a[r], bv[1]);
                ffma2(acc[r][2], a[r], bv[2]);
                ffma2(acc[r][3], a[r], bv[3]);
            }
        }
        const float scl = 0.022097086912079608f; // 1/(4*sqrt(128))
#pragma unroll
        for (int r = 0; r < 4; r++){
            float nr = N2[R + r];
            float4 o;
            o.x = -scl * (nr + N2[C+0] - 2.f * red2(acc[r][0]));
            o.y = -scl * (nr + N2[C+1] - 2.f * red2(acc[r][1]));
            o.z = -scl * (nr + N2[C+2] - 2.f * red2(acc[r][2]));
            o.w = -scl * (nr + N2[C+3] - 2.f * red2(acc[r][3]));
            *reinterpret_cast<float4*>(AFs + (R + r) * 68 + C) = o;
        }
    }
    __syncthreads();
    // pass4: softmax + minmax normalize; write af out; clamp into AFs
    {
        float* afo = out + AF_OFF + (size_t)win * 4096;
        for (int q = w * 8; q < w * 8 + 8; q++){
            float x0 = AFs[q*68+lane], x1 = AFs[q*68+lane+32];
            float mx = wredmax(fmaxf(x0, x1));
            float e0 = expf(x0 - mx), e1 = expf(x1 - mx);
            float s = wredsum(e0 + e1);
            float p0 = e0 / s, p1 = e1 / s;
            float mn  = wredmin(fminf(p0, p1));
            float mxv = wredmax(fmaxf(p0, p1));
            float den = mxv - mn + 1e-8f;
            float a0 = (p0 - mn) / den, a1 = (p1 - mn) / den;
            afo[q*64+lane]    = a0;
            afo[q*64+lane+32] = a1;
            AFs[q*68+lane]    = clampaf(a0);
            AFs[q*68+lane+32] = clampaf(a1);
        }
    }
    __syncthreads();
    // pass5: compactness per row; unrolled x4 min-pair loop, 8 fma chains
    {
        float* WD = QT2 + w * 128;
        float* WA = WD + 64;
        for (int q = w * 8; q < w * 8 + 8; q++){
            int k0 = lane, k1 = lane + 32;
            float f0 = AFs[q*68+k0], f1 = AFs[q*68+k1];
            float d0 = f0*DENS[k0], d1 = f1*DENS[k1];
            float a0 = f0*AREA[k0], a1 = f1*AREA[k1];
            WD[k0]=d0; WD[k1]=d1; WA[k0]=a0; WA[k1]=a1;
            __syncwarp();
            float m0 = d0*a0, m1 = d1*a1;
            float cqx = CX[q], cqy = CY[q], cq2 = C2[q];
            float di0 = cq2 + C2[k0] - 2.f*(cqx*CX[k0] + cqy*CY[k0]);
            float di1 = cq2 + C2[k1] - 2.f*(cqx*CX[k1] + cqy*CY[k1]);
            float ni   = d0*INER[k0] + d1*INER[k1] + m0*di0 + m1*di1;
            float saa  = m0*a0 + m1*a1;
            float sdaa = d0*a0*a0 + d1*a1*a1;
            float i0a=0.f,i0b=0.f,i0c=0.f,i0d=0.f;
            float i1a=0.f,i1b=0.f,i1c=0.f,i1d=0.f;
#pragma unroll 4
            for (int j = 0; j < 64; j += 4){
                float4 dj = *reinterpret_cast<float4*>(WD + j);
                float4 aj = *reinterpret_cast<float4*>(WA + j);
                i0a = fmaf(fminf(d0, dj.x), aj.x, i0a);
                i0b = fmaf(fminf(d0, dj.y), aj.y, i0b);
                i0c = fmaf(fminf(d0, dj.z), aj.z, i0c);
                i0d = fmaf(fminf(d0, dj.w), aj.w, i0d);
                i1a = fmaf(fminf(d1, dj.x), aj.x, i1a);
                i1b = fmaf(fminf(d1, dj.y), aj.y, i1b);
                i1c = fmaf(fminf(d1, dj.z), aj.z, i1c);
                i1d = fmaf(fminf(d1, dj.w), aj.w, i1d);
            }
            float in0 = (i0a + i0b) + (i0c + i0d);
            float in1 = (i1a + i1b) + (i1c + i1d);
            float mp_p = a0*in0 + a1*in1;
            ni  = wredsum(ni);
            float mp = wredsum(mp_p) - wredsum(sdaa);
            saa = wredsum(saa);
            if (lane == 0) COMP[q] = ((saa + mp) / 6.283185307179586f) / ni;
            __syncwarp();
        }
    }
    __syncthreads();
    // pass6: greedy clustering on warp 0 (7 steps, first-index argmax)
    if (w == 0){
        for (int it = 0; it < 7; it++){
            float s0 = COMP[lane]*SCv[lane], s1 = COMP[lane+32]*SCv[lane+32];
            float m = wredmax(fmaxf(s0, s1));
            int cand = 1000;
            if (s1 == m) cand = lane + 32;
            if (s0 == m) cand = lane;
#pragma unroll
            for (int o = 16; o; o >>= 1) cand = min(cand, __shfl_xor_sync(0xffffffffu, cand, o));
            float r0 = AFs[cand*68+lane], r1 = AFs[cand*68+lane+32];
            CLM[it*64+lane]    = SCv[lane]   * r0;
            CLM[it*64+lane+32] = SCv[lane+32]* r1;
            SCv[lane]    *= (1.f - r0);
            SCv[lane+32] *= (1.f - r1);
            if (lane == 0) out[CLR_OFF + win * 7 + it] = (float)cand;
            __syncwarp();
        }
        CLM[7*64+lane]    = SCv[lane];
        CLM[7*64+lane+32] = SCv[lane+32];
    }
    __syncthreads();
    // pass7: per-cluster stats + 2nd compactness (warp c = w)
    {
        int c = w;
        float* WD = QT2 + w * 128;
        float* WA = WD + 64;
        int k0 = lane, k1 = lane + 32;
        float m0 = CLM[c*64+k0], m1 = CLM[c*64+k1];
        float cd0 = m0*DENS[k0], cd1 = m1*DENS[k1];
        float ca0 = m0*AREA[k0], ca1 = m1*AREA[k1];
        float cm0 = cd0*ca0, cm1 = cd1*ca1;
        float Scm = wredsum(cm0 + cm1);
        float Sca = wredsum(ca0 + ca1);
        float Sx  = wredsum(cm0*CX[k0] + cm1*CX[k1]);
        float Sy  = wredsum(cm0*CY[k0] + cm1*CY[k1]);
        float ccx = Sx / (Scm + 1e-8f);
        float ccy = Sy / (Scm + 1e-8f);
        float cc2 = ccx*ccx + ccy*ccy;
        float di0 = cc2 + C2[k0] - 2.f*(ccx*CX[k0] + ccy*CY[k0]);
        float di1 = cc2 + C2[k1] - 2.f*(ccx*CX[k1] + ccy*CY[k1]);
        float ni   = wredsum(cd0*INER[k0] + cd1*INER[k1] + cm0*di0 + cm1*di1);
        float saa  = wredsum(cm0*ca0 + cm1*ca1);
        float sdaa = wredsum(cd0*ca0*ca0 + cd1*ca1*ca1);
        WD[k0]=cd0; WD[k1]=cd1; WA[k0]=ca0; WA[k1]=ca1;
        __syncwarp();
        float i0a=0.f,i0b=0.f,i0c=0.f,i0d=0.f;
        float i1a=0.f,i1b=0.f,i1c=0.f,i1d=0.f;
#pragma unroll 4
        for (int j = 0; j < 64; j += 4){
            float4 dj = *reinterpret_cast<float4*>(WD + j);
            float4 aj = *reinterpret_cast<float4*>(WA + j);
            i0a = fmaf(fminf(cd0, dj.x), aj.x, i0a);
            i0b = fmaf(fminf(cd0, dj.y), aj.y, i0b);
            i0c = fmaf(fminf(cd0, dj.z), aj.z, i0c);
            i0d = fmaf(fminf(cd0, dj.w), aj.w, i0d);
            i1a = fmaf(fminf(cd1, dj.x), aj.x, i1a);
            i1b = fmaf(fminf(cd1, dj.y), aj.y, i1b);
            i1c = fmaf(fminf(cd1, dj.z), aj.z, i1c);
            i1d = fmaf(fminf(cd1, dj.w), aj.w, i1d);
        }
        float in0 = (i0a + i0b) + (i0c + i0d);
        float in1 = (i1a + i1b) + (i1c + i1d);
        float mp = wredsum(ca0*in0 + ca1*in1) - sdaa;
        float Sclm = wredsum(m0 + m1);
        CLMM[c*64+k0] = m0 / (Sclm + 1e-8f);
        CLMM[c*64+k1] = m1 / (Sclm + 1e-8f);
        if (lane == 0){
            RS[c] = Sclm / (Sclm + 1e-8f);
            float* geo = out + CLGEO_OFF + win * 48 + c * 6;
            geo[0] = Scm / (Sca + 1e-8f);
            geo[1] = Scm;
            geo[2] = Sca;
            geo[3] = ni;
            geo[4] = ccx; geo[5] = ccy;
            out[CLCOMP_OFF + win * 8 + c] = ((saa + mp) / 6.283185307179586f) / ni;
        }
    }
    __syncthreads();
    // write cl_m + sc_m
    for (int i = t; i < 512; i += 256) out[CLM_OFF + win * 512 + i] = CLM[i];
    if (t < 64) out[SCM_OFF + win * 64 + t] = CLM[448 + t];
    // epilogue
    {
        const float* Xf = in_f + (size_t)win * TOK;
        const float* Hh = g_h  + (size_t)win * TOK;
        const float* Ff = g_f  + (size_t)win * TOK;
        int d = t & 127, cg = (t >> 7) * 4;
        float p0[4] = {0,0,0,0}, p1[4] = {0,0,0,0}, p2[4] = {0,0,0,0};
#pragma unroll 2
        for (int k = 0; k < 64; k++){
            float xa = Xf[k*128+d], xh = Hh[k*128+d], xf = Ff[k*128+d];
#pragma unroll
            for (int cc = 0; cc < 4; cc++){
                float mm = CLMM[(cg+cc)*64+k];
                p0[cc] = fmaf(mm, xa, p0[cc]);
                p1[cc] = fmaf(mm, xh, p1[cc]);
                p2[cc] = fmaf(mm, xf, p2[cc]);
            }
        }
        float* P1t = sm;           // [128][8]
        float* P2t = sm + 1024;
        float* T2t = sm + 2048;
#pragma unroll
        for (int cc = 0; cc < 4; cc++){
            P1t[d*8 + cg + cc] = p1[cc];
            P2t[d*8 + cg + cc] = p2[cc];
        }
        __syncthreads();
        ull t1p[2] = {0ull, 0ull}, t2p[2] = {0ull, 0ull};
#pragma unroll 2
        for (int k = 0; k < 128; k++){
            ull w2d = dup2(W2[k*128+d]);
            ull wvd = dup2(Wv[k*128+d]);
            ull p1a = *reinterpret_cast<const ull*>(P1t + k*8 + cg);
            ull p1b = *reinterpret_cast<const ull*>(P1t + k*8 + cg + 2);
            ull p2a = *reinterpret_cast<const ull*>(P2t + k*8 + cg);
            ull p2b = *reinterpret_cast<const ull*>(P2t + k*8 + cg + 2);
            ffma2(t1p[0], p1a, w2d); ffma2(t1p[1], p1b, w2d);
            ffma2(t2p[0], p2a, wvd); ffma2(t2p[1], p2b, wvd);
        }
        float t2v[4];
        unpack2(t2p[0], t2v[0], t2v[1]);
        unpack2(t2p[1], t2v[2], t2v[3]);
#pragma unroll
        for (int cc = 0; cc < 4; cc++) T2t[d*8 + cg + cc] = t2v[cc];
        __syncthreads();
        ull t3p[2] = {0ull, 0ull};
#pragma unroll 2
        for (int k = 0; k < 128; k++){
            ull wfd = dup2(Wfc[k*128+d]);
            ull ta = *reinterpret_cast<const ull*>(T2t + k*8 + cg);
            ull tb = *reinterpret_cast<const ull*>(T2t + k*8 + cg + 2);
            ffma2(t3p[0], ta, wfd); ffma2(t3p[1], tb, wfd);
        }
        float t1v[4], t3v[4];
        unpack2(t1p[0], t1v[0], t1v[1]);
        unpack2(t1p[1], t1v[2], t1v[3]);
        unpack2(t3p[0], t3v[0], t3v[1]);
        unpack2(t3p[1], t3v[2], t3v[3]);
        float b2d = b2[d], bfd = bfc[d];
#pragma unroll
        for (int cc = 0; cc < 4; cc++)
            out[CLF_OFF + (size_t)win * 1024 + (cg+cc) * 128 + d] =
                p0[cc] + t1v[cc] + RS[cg+cc] * b2d + t3v[cc] + bfd;
    }
}

extern "C" void kernel_launch(void* const* d_in, const int* in_sizes, int n_in,
                              void* d_out, int out_size){
    (void)in_sizes; (void)n_in; (void)out_size;
    const float* in_f   = (const float*)d_in[0];
    const float* in_geo = (const float*)d_in[1];
    const float* W1  = (const float*)d_in[2];
    const float* b1  = (const float*)d_in[3];
    const float* W2  = (const float*)d_in[4];
    const float* b2  = (const float*)d_in[5];
    const float* Wfc = (const float*)d_in[6];
    const float* bfc = (const float*)d_in[7];
    const float* Wq  = (const float*)d_in[8];
    const float* Wv  = (const float*)d_in[9];
    float* out = (float*)d_out;

    cudaFuncSetAttribute(k_mlp,  cudaFuncAttributeMaxDynamicSharedMemorySize, 99328);
    cudaFuncSetAttribute(k_main, cudaFuncAttributeMaxDynamicSharedMemorySize, 57632);

    k_stat<<<2048, 256>>>(in_f);
    k_red<<<32, 256>>>(0);
    k_mlp<<<2048, 256, 99328>>>(in_f, W1, b1, Wq);
    k_red<<<32, 256>>>(1);
    k_main<<<2048, 256, 57632>>>(in_f, in_geo, W2, b2, Wfc, bfc, Wv, out);
}

// round 10
// speedup vs baseline: 1.3409x; 1.3409x over previous
#include <cuda_runtime.h>

// b=8, nw=256, nn=64, d=128, G=4. windows = 2048, TOK = 64*128 = 8192.
#define NTW 2048
#define TOK 8192
typedef unsigned long long ull;

// Scratch (device globals; no cudaMalloc allowed)
__device__ float g_h [NTW * TOK];   // leaky(_f@W1 + b1)
__device__ float g_qp[NTW * TOK];   // _f@Wq (pre group-norm)
__device__ float g_pf[NTW * 8];
__device__ float g_pq[NTW * 8];
__device__ float g_mu[2][32];
__device__ float g_rs[2][32];

// Output layout: flattened float32, tuple order
#define CLF_OFF    0
#define CLM_OFF    2097152
#define CLGEO_OFF  3145728
#define CLR_OFF    3244032
#define CLCOMP_OFF 3258368
#define AF_OFF     3274752
#define SCM_OFF    11663360
#define Q_OFF      11794432

__device__ __forceinline__ float wredsum(float v){
#pragma unroll
    for (int o = 16; o; o >>= 1) v += __shfl_xor_sync(0xffffffffu, v, o);
    return v;
}
__device__ __forceinline__ float wredmax(float v){
#pragma unroll
    for (int o = 16; o; o >>= 1) v = fmaxf(v, __shfl_xor_sync(0xffffffffu, v, o));
    return v;
}
__device__ __forceinline__ float wredmin(float v){
#pragma unroll
    for (int o = 16; o; o >>= 1) v = fminf(v, __shfl_xor_sync(0xffffffffu, v, o));
    return v;
}
__device__ __forceinline__ float clampaf(float v){
    return fminf(fmaxf(v, 1e-5f), 0.99999f);
}

// ---- packed fp32x2 helpers ----
__device__ __forceinline__ void ffma2(ull& acc, ull a, ull b){
    asm("fma.rn.f32x2 %0, %1, %2, %0;" : "+l"(acc) : "l"(a), "l"(b));
}
__device__ __forceinline__ ull dup2(float x){
    ull r; asm("mov.b64 %0, {%1, %1};" : "=l"(r) : "f"(x)); return r;
}
__device__ __forceinline__ void unpack2(ull v, float& lo, float& hi){
    asm("mov.b64 {%0, %1}, %2;" : "=f"(lo), "=f"(hi) : "l"(v));
}
__device__ __forceinline__ float red2(ull v){
    float lo, hi; unpack2(v, lo, hi); return lo + hi;
}

// ============================================================================
// K1: per-window partial stats of in_f per channel group
// ============================================================================
__global__ void __launch_bounds__(256) k_stat(const float* __restrict__ in_f){
    __shared__ float sp[256][2];
    int win = blockIdx.x, t = threadIdx.x;
    const float* X = in_f + (size_t)win * TOK;
    int c = t & 127, h = t >> 7;
    float s = 0.f, ss = 0.f;
    for (int r = h; r < 64; r += 2){
        float v = X[r * 128 + c];
        s += v; ss = fmaf(v, v, ss);
    }
    sp[t][0] = s; sp[t][1] = ss;
    __syncthreads();
    if (t < 4){
        float S = 0.f, SS = 0.f;
        for (int hh = 0; hh < 2; hh++)
            for (int j = 0; j < 32; j++){
                int tt = hh * 128 + t * 32 + j;
                S += sp[tt][0]; SS += sp[tt][1];
            }
        g_pf[win * 8 + t * 2]     = S;
        g_pf[win * 8 + t * 2 + 1] = SS;
    }
}

// ============================================================================
// K2/K4: reduce partials over 256 windows -> mu, rsqrt(var+eps) per (b,g)
// ============================================================================
__global__ void __launch_bounds__(256) k_red(int which){
    __shared__ float sh[256][2];
    int bg = blockIdx.x, t = threadIdx.x;
    const float* P = which ? g_pq : g_pf;
    int win = (bg >> 2) * 256 + t, g = bg & 3;
    sh[t][0] = P[win * 8 + g * 2];
    sh[t][1] = P[win * 8 + g * 2 + 1];
    __syncthreads();
    for (int st = 128; st > 0; st >>= 1){
        if (t < st){ sh[t][0] += sh[t + st][0]; sh[t][1] += sh[t + st][1]; }
        __syncthreads();
    }
    if (t == 0){
        const float N = 524288.0f; // 256*64*32
        float m = sh[0][0] / N;
        float v = sh[0][1] / N - m * m;
        g_mu[which][bg] = m;
        g_rs[which][bg] = rsqrtf(v + 1e-3f);
    }
}

// ============================================================================
// K3: per-window: h = leaky(_f@W1+b1), q_pre = _f@Wq, q-stat partials.
// _f is built in smem only (no global round-trip).
// At2[kk][2*r + (k&1)] pitch 132; Ws2[kk][2*c + (k&1)] pitch 256.
// dynamic smem = (64*132 + 64*256)*4 = 99328 B.
// ============================================================================
__global__ void __launch_bounds__(256) k_mlp(const float* __restrict__ in_f,
                      const float* __restrict__ W1, const float* __restrict__ b1,
                      const float* __restrict__ Wq){
    extern __shared__ float smm[];
    float* At2 = smm;             // 64 * 132 = 8448
    float* Ws2 = smm + 8448;      // 64 * 256 = 16384
    __shared__ float sp[256][2];

    int win = blockIdx.x, t = threadIdx.x, b = win >> 8;

    float mu[4], rv[4];
#pragma unroll
    for (int g = 0; g < 4; g++){ mu[g] = g_mu[0][b*4+g]; rv[g] = g_rs[0][b*4+g]; }

    const float* X = in_f + (size_t)win * TOK;
    {
        int c = t & 127, g = c >> 5;
        float m = mu[g], r = rv[g];
        int cbase = (c >> 1) * 132 + (c & 1);
        for (int i = t; i < TOK; i += 256){
            float v = (X[i] - m) * r;
            At2[cbase + ((i >> 7) << 1)] = v;
        }
    }
    for (int i = t; i < 16384; i += 256){
        int k = i >> 7, c = i & 127;
        Ws2[(k >> 1) * 256 + (c << 1) + (k & 1)] = W1[i];
    }
    __syncthreads();

    int rb = (t >> 5) * 8, cb = (t & 31) * 4;
    ull acc[8][4];
#pragma unroll
    for (int r = 0; r < 8; r++)
#pragma unroll
        for (int c = 0; c < 4; c++) acc[r][c] = 0ull;

    for (int kk = 0; kk < 64; kk++){
        const float* ab = At2 + kk * 132 + rb * 2;
        ulonglong2 a01 = *reinterpret_cast<const ulonglong2*>(ab);
        ulonglong2 a23 = *reinterpret_cast<const ulonglong2*>(ab + 4);
        ulonglong2 a45 = *reinterpret_cast<const ulonglong2*>(ab + 8);
        ulonglong2 a67 = *reinterpret_cast<const ulonglong2*>(ab + 12);
        const float* wb = Ws2 + kk * 256 + cb * 2;
        ulonglong2 w01 = *reinterpret_cast<const ulonglong2*>(wb);
        ulonglong2 w23 = *reinterpret_cast<const ulonglong2*>(wb + 4);
        ull a[8] = {a01.x,a01.y,a23.x,a23.y,a45.x,a45.y,a67.x,a67.y};
        ull w[4] = {w01.x,w01.y,w23.x,w23.y};
#pragma unroll
        for (int r = 0; r < 8; r++){
            ffma2(acc[r][0], a[r], w[0]);
            ffma2(acc[r][1], a[r], w[1]);
            ffma2(acc[r][2], a[r], w[2]);
            ffma2(acc[r][3], a[r], w[3]);
        }
    }
    {
        float4 bv = *reinterpret_cast<const float4*>(b1 + cb);
        float bb[4] = {bv.x, bv.y, bv.z, bv.w};
        float* Ho = g_h + (size_t)win * TOK;
#pragma unroll
        for (int r = 0; r < 8; r++){
            float4 o; float v;
            v = red2(acc[r][0]) + bb[0]; o.x = v >= 0.f ? v : 0.01f * v;
            v = red2(acc[r][1]) + bb[1]; o.y = v >= 0.f ? v : 0.01f * v;
            v = red2(acc[r][2]) + bb[2]; o.z = v >= 0.f ? v : 0.01f * v;
            v = red2(acc[r][3]) + bb[3]; o.w = v >= 0.f ? v : 0.01f * v;
            *reinterpret_cast<float4*>(Ho + (rb + r) * 128 + cb) = o;
        }
    }
    __syncthreads();
    for (int i = t; i < 16384; i += 256){
        int k = i >> 7, c = i & 127;
        Ws2[(k >> 1) * 256 + (c << 1) + (k & 1)] = Wq[i];
    }
    __syncthreads();

#pragma unroll
    for (int r = 0; r < 8; r++)
#pragma unroll
        for (int c = 0; c < 4; c++) acc[r][c] = 0ull;
    for (int kk = 0; kk < 64; kk++){
        const float* ab = At2 + kk * 132 + rb * 2;
        ulonglong2 a01 = *reinterpret_cast<const ulonglong2*>(ab);
        ulonglong2 a23 = *reinterpret_cast<const ulonglong2*>(ab + 4);
        ulonglong2 a45 = *reinterpret_cast<const ulonglong2*>(ab + 8);
        ulonglong2 a67 = *reinterpret_cast<const ulonglong2*>(ab + 12);
        const float* wb = Ws2 + kk * 256 + cb * 2;
        ulonglong2 w01 = *reinterpret_cast<const ulonglong2*>(wb);
        ulonglong2 w23 = *reinterpret_cast<const ulonglong2*>(wb + 4);
        ull a[8] = {a01.x,a01.y,a23.x,a23.y,a45.x,a45.y,a67.x,a67.y};
        ull w[4] = {w01.x,w01.y,w23.x,w23.y};
#pragma unroll
        for (int r = 0; r < 8; r++){
            ffma2(acc[r][0], a[r], w[0]);
            ffma2(acc[r][1], a[r], w[1]);
            ffma2(acc[r][2], a[r], w[2]);
            ffma2(acc[r][3], a[r], w[3]);
        }
    }
    {
        float* Qo = g_qp + (size_t)win * TOK;
        float s = 0.f, ss = 0.f;
#pragma unroll
        for (int r = 0; r < 8; r++){
            float4 o;
            o.x = red2(acc[r][0]); o.y = red2(acc[r][1]);
            o.z = red2(acc[r][2]); o.w = red2(acc[r][3]);
            *reinterpret_cast<float4*>(Qo + (rb + r) * 128 + cb) = o;
            s  += o.x + o.y + o.z + o.w;
            ss += o.x*o.x + o.y*o.y + o.z*o.z + o.w*o.w;
        }
        sp[t][0] = s; sp[t][1] = ss;
    }
    __syncthreads();
    if (t < 4){
        float S = 0.f, SS = 0.f;
        for (int w2 = 0; w2 < 8; w2++)
            for (int j = 0; j < 8; j++){
                int tt = w2 * 32 + t * 8 + j;
                S += sp[tt][0]; SS += sp[tt][1];
            }
        g_pq[win * 8 + t * 2]     = S;
        g_pq[win * 8 + t * 2 + 1] = SS;
    }
}

// ============================================================================
// K5: per-window mega kernel. dynamic smem = 57632 B.
// ============================================================================
__global__ void __launch_bounds__(256) k_main(const float* __restrict__ in_f,
        const float* __restrict__ in_geo,
        const float* __restrict__ W2,  const float* __restrict__ b2,
        const float* __restrict__ Wfc, const float* __restrict__ bfc,
        const float* __restrict__ Wv,  float* __restrict__ out){
    extern __shared__ float sm[];
    float* QT2  = sm;            // 64*132 = 8448; later reused as scratch
    float* AFs  = sm + 8448;     // [64][68]
    float* DENS = sm + 12800;
    float* AREA = sm + 12864;
    float* INER = sm + 12928;
    float* CX   = sm + 12992;
    float* CY   = sm + 13056;
    float* C2   = sm + 13120;
    float* N2   = sm + 13184;
    float* COMP = sm + 13248;
    float* SCv  = sm + 13312;
    float* CLM  = sm + 13376;    // [8][64]
    float* CLMM = sm + 13888;    // [8][64]
    float* RS   = sm + 14400;    // [8]

    int win = blockIdx.x, t = threadIdx.x;
    int w = t >> 5, lane = t & 31;
    int b = win >> 8;

    if (t < 64){
        const float* gp = in_geo + (size_t)win * 384 + t * 6;
        float dn = gp[0], ar = gp[2], ii = gp[3], x = gp[4], y = gp[5];
        DENS[t]=dn; AREA[t]=ar; INER[t]=ii; CX[t]=x; CY[t]=y; C2[t]=x*x+y*y;
        SCv[t]=1.f;
    }
    // pass1: normalize q_pre -> QT2 (k-pair interleaved) + q out
    {
        float mu[4], rv[4];
#pragma unroll
        for (int g = 0; g < 4; g++){ mu[g]=g_mu[1][b*4+g]; rv[g]=g_rs[1][b*4+g]; }
        const float* Qp = g_qp + (size_t)win * TOK;
        float* Qo = out + Q_OFF + (size_t)win * TOK;
        int c = t & 127, g = c >> 5;
        float m = mu[g], r = rv[g];
        int cbase = (c >> 1) * 132 + (c & 1);
        for (int i = t; i < TOK; i += 256){
            float v = (Qp[i] - m) * r;
            Qo[i] = v;
            QT2[cbase + ((i >> 7) << 1)] = v;
        }
    }
    __syncthreads();
    // pass2: n2 per row
    for (int q = w * 8; q < w * 8 + 8; q++){
        float s = 0.f;
        for (int c = lane; c < 128; c += 32){
            float v = QT2[(c >> 1) * 132 + (q << 1) + (c & 1)];
            s = fmaf(v, v, s);
        }
        s = wredsum(s);
        if (lane == 0) N2[q] = s;
    }
    __syncthreads();
    // pass3: Gram -> logits into AFs (f32x2)
    {
        int ty = t >> 4, tx = t & 15;
        int R = 4 * ty, C = 4 * tx;
        ull acc[4][4];
#pragma unroll
        for (int r = 0; r < 4; r++)
#pragma unroll
            for (int c = 0; c < 4; c++) acc[r][c] = 0ull;
        for (int kk = 0; kk < 64; kk++){
            const float* base = QT2 + kk * 132;
            ulonglong2 aa0 = *reinterpret_cast<const ulonglong2*>(base + R * 2);
            ulonglong2 aa1 = *reinterpret_cast<const ulonglong2*>(base + R * 2 + 4);
            ulonglong2 bb0 = *reinterpret_cast<const ulonglong2*>(base + C * 2);
            ulonglong2 bb1 = *reinterpret_cast<const ulonglong2*>(base + C * 2 + 4);
            ull a[4]  = {aa0.x, aa0.y, aa1.x, aa1.y};
            ull bv[4] = {bb0.x, bb0.y, bb1.x, bb1.y};
#pragma unroll
            for (int r = 0; r < 4; r++){
                ffma2(acc[r][0], a[r], bv[0]);
                ffma2(acc[r][1], a[r], bv[1]);
                ffma2(acc[r][2], a[r], bv[2]);
                ffma2(acc[r][3], a[r], bv[3]);
            }
        }
        const float scl = 0.022097086912079608f; // 1/(4*sqrt(128))
#pragma unroll
        for (int r = 0; r < 4; r++){
            float nr = N2[R + r];
            float4 o;
            o.x = -scl * (nr + N2[C+0] - 2.f * red2(acc[r][0]));
            o.y = -scl * (nr + N2[C+1] - 2.f * red2(acc[r][1]));
            o.z = -scl * (nr + N2[C+2] - 2.f * red2(acc[r][2]));
            o.w = -scl * (nr + N2[C+3] - 2.f * red2(acc[r][3]));
            *reinterpret_cast<float4*>(AFs + (R + r) * 68 + C) = o;
        }
    }
    __syncthreads();
    // pass4: softmax + minmax normalize; write af out; clamp into AFs
    {
        float* afo = out + AF_OFF + (size_t)win * 4096;
        for (int q = w * 8; q < w * 8 + 8; q++){
            float x0 = AFs[q*68+lane], x1 = AFs[q*68+lane+32];
            float mx = wredmax(fmaxf(x0, x1));
            float e0 = expf(x0 - mx), e1 = expf(x1 - mx);
            float s = wredsum(e0 + e1);
            float p0 = e0 / s, p1 = e1 / s;
            float mn  = wredmin(fminf(p0, p1));
            float mxv = wredmax(fmaxf(p0, p1));
            float den = mxv - mn + 1e-8f;
            float a0 = (p0 - mn) / den, a1 = (p1 - mn) / den;
            afo[q*64+lane]    = a0;
            afo[q*64+lane+32] = a1;
            AFs[q*68+lane]    = clampaf(a0);
            AFs[q*68+lane+32] = clampaf(a1);
        }
    }
    __syncthreads();
    // pass5: compactness per row (warp w: rows w*8..w*8+7)
    {
        float* WD = QT2 + w * 128;
        float* WA = WD + 64;
        for (int q = w * 8; q < w * 8 + 8; q++){
            int k0 = lane, k1 = lane + 32;
            float f0 = AFs[q*68+k0], f1 = AFs[q*68+k1];
            float d0 = f0*DENS[k0], d1 = f1*DENS[k1];
            float a0 = f0*AREA[k0], a1 = f1*AREA[k1];
            WD[k0]=d0; WD[k1]=d1; WA[k0]=a0; WA[k1]=a1;
            __syncwarp();
            float m0 = d0*a0, m1 = d1*a1;
            float cqx = CX[q], cqy = CY[q], cq2 = C2[q];
            float di0 = cq2 + C2[k0] - 2.f*(cqx*CX[k0] + cqy*CY[k0]);
            float di1 = cq2 + C2[k1] - 2.f*(cqx*CX[k1] + cqy*CY[k1]);
            float ni   = d0*INER[k0] + d1*INER[k1] + m0*di0 + m1*di1;
            float saa  = m0*a0 + m1*a1;
            float sdaa = d0*a0*a0 + d1*a1*a1;
            float in0 = 0.f, in1 = 0.f;
            for (int j = 0; j < 64; j++){
                float dj = WD[j], aj = WA[j];
                in0 += fminf(d0, dj) * aj;
                in1 += fminf(d1, dj) * aj;
            }
            float mp_p = a0*in0 + a1*in1;
            ni  = wredsum(ni);
            float mp = wredsum(mp_p) - wredsum(sdaa);
            saa = wredsum(saa);
            if (lane == 0) COMP[q] = ((saa + mp) / 6.283185307179586f) / ni;
            __syncwarp();
        }
    }
    __syncthreads();
    // pass6: greedy clustering on warp 0 (7 steps, first-index argmax)
    if (w == 0){
        for (int it = 0; it < 7; it++){
            float s0 = COMP[lane]*SCv[lane], s1 = COMP[lane+32]*SCv[lane+32];
            float m = wredmax(fmaxf(s0, s1));
            int cand = 1000;
            if (s1 == m) cand = lane + 32;
            if (s0 == m) cand = lane;
#pragma unroll
            for (int o = 16; o; o >>= 1) cand = min(cand, __shfl_xor_sync(0xffffffffu, cand, o));
            float r0 = AFs[cand*68+lane], r1 = AFs[cand*68+lane+32];
            CLM[it*64+lane]    = SCv[lane]   * r0;
            CLM[it*64+lane+32] = SCv[lane+32]* r1;
            SCv[lane]    *= (1.f - r0);
            SCv[lane+32] *= (1.f - r1);
            if (lane == 0) out[CLR_OFF + win * 7 + it] = (float)cand;
            __syncwarp();
        }
        CLM[7*64+lane]    = SCv[lane];
        CLM[7*64+lane+32] = SCv[lane+32];
    }
    __syncthreads();
    // pass7: per-cluster stats + 2nd compactness (warp c = w)
    {
        int c = w;
        float* WD = QT2 + w * 128;
        float* WA = WD + 64;
        int k0 = lane, k1 = lane + 32;
        float m0 = CLM[c*64+k0], m1 = CLM[c*64+k1];
        float cd0 = m0*DENS[k0], cd1 = m1*DENS[k1];
        float ca0 = m0*AREA[k0], ca1 = m1*AREA[k1];
        float cm0 = cd0*ca0, cm1 = cd1*ca1;
        float Scm = wredsum(cm0 + cm1);
        float Sca = wredsum(ca0 + ca1);
        float Sx  = wredsum(cm0*CX[k0] + cm1*CX[k1]);
        float Sy  = wredsum(cm0*CY[k0] + cm1*CY[k1]);
        float ccx = Sx / (Scm + 1e-8f);
        float ccy = Sy / (Scm + 1e-8f);
        float cc2 = ccx*ccx + ccy*ccy;
        float di0 = cc2 + C2[k0] - 2.f*(ccx*CX[k0] + ccy*CY[k0]);
        float di1 = cc2 + C2[k1] - 2.f*(ccx*CX[k1] + ccy*CY[k1]);
        float ni   = wredsum(cd0*INER[k0] + cd1*INER[k1] + cm0*di0 + cm1*di1);
        float saa  = wredsum(cm0*ca0 + cm1*ca1);
        float sdaa = wredsum(cd0*ca0*ca0 + cd1*ca1*ca1);
        WD[k0]=cd0; WD[k1]=cd1; WA[k0]=ca0; WA[k1]=ca1;
        __syncwarp();
        float in0 = 0.f, in1 = 0.f;
        for (int j = 0; j < 64; j++){
            float dj = WD[j], aj = WA[j];
            in0 += fminf(cd0, dj) * aj;
            in1 += fminf(cd1, dj) * aj;
        }
        float mp = wredsum(ca0*in0 + ca1*in1) - sdaa;
        float Sclm = wredsum(m0 + m1);
        CLMM[c*64+k0] = m0 / (Sclm + 1e-8f);
        CLMM[c*64+k1] = m1 / (Sclm + 1e-8f);
        if (lane == 0){
            RS[c] = Sclm / (Sclm + 1e-8f);
            float* geo = out + CLGEO_OFF + win * 48 + c * 6;
            geo[0] = Scm / (Sca + 1e-8f);
            geo[1] = Scm;
            geo[2] = Sca;
            geo[3] = ni;
            geo[4] = ccx; geo[5] = ccy;
            out[CLCOMP_OFF + win * 8 + c] = ((saa + mp) / 6.283185307179586f) / ni;
        }
    }
    __syncthreads();
    // write cl_m + sc_m
    for (int i = t; i < 512; i += 256) out[CLM_OFF + win * 512 + i] = CLM[i];
    if (t < 64) out[SCM_OFF + win * 64 + t] = CLM[448 + t];
    // epilogue: cl_f = cl_mm@in_f + (cl_mm@h)@W2 + rs*b2 + ((cl_mm@_f)@Wv)@Wfc + bfc
    // with cl_mm@_f derived algebraically: p2 = rv0*(p0 - mu0*RS[c])  (per channel d)
    {
        const float* Xf = in_f + (size_t)win * TOK;
        const float* Hh = g_h  + (size_t)win * TOK;
        int d = t & 127, cg = (t >> 7) * 4;
        float p0[4] = {0,0,0,0}, p1[4] = {0,0,0,0};
        for (int k = 0; k < 64; k++){
            float xa = Xf[k*128+d], xh = Hh[k*128+d];
#pragma unroll
            for (int cc = 0; cc < 4; cc++){
                float mm = CLMM[(cg+cc)*64+k];
                p0[cc] = fmaf(mm, xa, p0[cc]);
                p1[cc] = fmaf(mm, xh, p1[cc]);
            }
        }
        float mu0 = g_mu[0][b*4 + (d >> 5)];
        float rv0 = g_rs[0][b*4 + (d >> 5)];
        float p2[4];
#pragma unroll
        for (int cc = 0; cc < 4; cc++)
            p2[cc] = rv0 * (p0[cc] - mu0 * RS[cg+cc]);
        float* P1t = sm;           // [128][8]
        float* P2t = sm + 1024;
        float* T2t = sm + 2048;
#pragma unroll
        for (int cc = 0; cc < 4; cc++){
            P1t[d*8 + cg + cc] = p1[cc];
            P2t[d*8 + cg + cc] = p2[cc];
        }
        __syncthreads();
        ull t1p[2] = {0ull, 0ull}, t2p[2] = {0ull, 0ull};
        for (int k = 0; k < 128; k++){
            ull w2d = dup2(W2[k*128+d]);
            ull wvd = dup2(Wv[k*128+d]);
            ull p1a = *reinterpret_cast<const ull*>(P1t + k*8 + cg);
            ull p1b = *reinterpret_cast<const ull*>(P1t + k*8 + cg + 2);
            ull p2a = *reinterpret_cast<const ull*>(P2t + k*8 + cg);
            ull p2b = *reinterpret_cast<const ull*>(P2t + k*8 + cg + 2);
            ffma2(t1p[0], p1a, w2d); ffma2(t1p[1], p1b, w2d);
            ffma2(t2p[0], p2a, wvd); ffma2(t2p[1], p2b, wvd);
        }
        float t2v[4];
        unpack2(t2p[0], t2v[0], t2v[1]);
        unpack2(t2p[1], t2v[2], t2v[3]);
#pragma unroll
        for (int cc = 0; cc < 4; cc++) T2t[d*8 + cg + cc] = t2v[cc];
        __syncthreads();
        ull t3p[2] = {0ull, 0ull};
        for (int k = 0; k < 128; k++){
            ull wfd = dup2(Wfc[k*128+d]);
            ull ta = *reinterpret_cast<const ull*>(T2t + k*8 + cg);
            ull tb = *reinterpret_cast<const ull*>(T2t + k*8 + cg + 2);
            ffma2(t3p[0], ta, wfd); ffma2(t3p[1], tb, wfd);
        }
        float t1v[4], t3v[4];
        unpack2(t1p[0], t1v[0], t1v[1]);
        unpack2(t1p[1], t1v[2], t1v[3]);
        unpack2(t3p[0], t3v[0], t3v[1]);
        unpack2(t3p[1], t3v[2], t3v[3]);
        float b2d = b2[d], bfd = bfc[d];
#pragma unroll
        for (int cc = 0; cc < 4; cc++)
            out[CLF_OFF + (size_t)win * 1024 + (cg+cc) * 128 + d] =
                p0[cc] + t1v[cc] + RS[cg+cc] * b2d + t3v[cc] + bfd;
    }
}

extern "C" void kernel_launch(void* const* d_in, const int* in_sizes, int n_in,
                              void* d_out, int out_size){
    (void)in_sizes; (void)n_in; (void)out_size;
    const float* in_f   = (const float*)d_in[0];
    const float* in_geo = (const float*)d_in[1];
    const float* W1  = (const float*)d_in[2];
    const float* b1  = (const float*)d_in[3];
    const float* W2  = (const float*)d_in[4];
    const float* b2  = (const float*)d_in[5];
    const float* Wfc = (const float*)d_in[6];
    const float* bfc = (const float*)d_in[7];
    const float* Wq  = (const float*)d_in[8];
    const float* Wv  = (const float*)d_in[9];
    float* out = (float*)d_out;

    cudaFuncSetAttribute(k_mlp,  cudaFuncAttributeMaxDynamicSharedMemorySize, 99328);
    cudaFuncSetAttribute(k_main, cudaFuncAttributeMaxDynamicSharedMemorySize, 57632);

    k_stat<<<2048, 256>>>(in_f);
    k_red<<<32, 256>>>(0);
    k_mlp<<<2048, 256, 99328>>>(in_f, W1, b1, Wq);
    k_red<<<32, 256>>>(1);
    k_main<<<2048, 256, 57632>>>(in_f, in_geo, W2, b2, Wfc, bfc, Wv, out);
}